// round 15
// baseline (speedup 1.0000x reference)
#include <cuda_runtime.h>
#include <cuda_fp16.h>
#include <cstdint>
#include <math.h>

#define TOKENS 2048
#define HIDDEN 2048
#define INTER  1408
#define NEXP   8
#define KTH    64          // k elements per tile (halfs) = 128B of data per row
#define STAGES 3

// gateup tiles: A [64m][64k] stride 144B; Bg/Bu [64k][64n] stride 144B
#define AT_B      (64 * 144)               // 9216
#define BGU_B     (64 * 144)               // 9216 per gate/up tile
#define STAGE_GU  (AT_B + 2 * BGU_B)       // 27648
#define SMEM_GU   (256 + STAGES * STAGE_GU)   // 83200
// down tiles: A [64m][64k] stride 144B; B [64k][128n] stride 272B
#define BDN_B     (64 * 272)               // 17408
#define STAGE_DN  (AT_B + BDN_B)           // 26624
#define SMEM_DN   (256 + STAGES * STAGE_DN)   // 80128

// ---------------- device scratch (no allocation) ----------------
__device__ int    g_counts[NEXP];
__device__ int    g_pairs[NEXP * TOKENS];                 // encoded (t<<1)|slot
__device__ float  g_wts[TOKENS * 2];                      // combine weight per (t,slot)
__device__ __half g_x_h[(size_t)TOKENS * HIDDEN];         // x in fp16
__device__ __half g_wg_h[(size_t)NEXP * HIDDEN * INTER];  // w_gate fp16, [e][k][n]
__device__ __half g_wu_h[(size_t)NEXP * HIDDEN * INTER];  // w_up   fp16, [e][k][n]
__device__ __half g_wd_h[(size_t)NEXP * INTER * HIDDEN];  // w_down fp16, [e][k][n]
__device__ __half g_hbuf_h[(size_t)TOKENS * 2 * INTER];   // gated intermediate fp16

// m16n8k16 fp16 MMA, fp32 accumulate (standard PTX, sm_80+)
__device__ __forceinline__ void mma_f16(float* c, const uint32_t* a,
                                        uint32_t b0, uint32_t b1) {
    asm volatile(
        "mma.sync.aligned.m16n8k16.row.col.f32.f16.f16.f32 "
        "{%0,%1,%2,%3}, {%4,%5,%6,%7}, {%8,%9}, {%0,%1,%2,%3};"
        : "+f"(c[0]), "+f"(c[1]), "+f"(c[2]), "+f"(c[3])
        : "r"(a[0]), "r"(a[1]), "r"(a[2]), "r"(a[3]), "r"(b0), "r"(b1));
}

__device__ __forceinline__ void ldsm4(uint32_t* r, uint32_t addr) {
    asm volatile("ldmatrix.sync.aligned.m8n8.x4.shared.b16 {%0,%1,%2,%3}, [%4];"
        : "=r"(r[0]), "=r"(r[1]), "=r"(r[2]), "=r"(r[3]) : "r"(addr));
}
// transposed variant: stored [k][n] (n contiguous), yields col-major B fragment
__device__ __forceinline__ void ldsm4t(uint32_t* r, uint32_t addr) {
    asm volatile("ldmatrix.sync.aligned.m8n8.x4.trans.shared.b16 {%0,%1,%2,%3}, [%4];"
        : "=r"(r[0]), "=r"(r[1]), "=r"(r[2]), "=r"(r[3]) : "r"(addr));
}

__device__ __forceinline__ void cp16(uint32_t dst, const void* src, int sz) {
    asm volatile("cp.async.cg.shared.global [%0], [%1], 16, %2;"
                 :: "r"(dst), "l"(src), "r"(sz) : "memory");
}
#define CP_COMMIT() asm volatile("cp.async.commit_group;" ::: "memory")
#define CP_WAIT1()  asm volatile("cp.async.wait_group 1;" ::: "memory")

__device__ __forceinline__ uint32_t hpack(float a, float b) {
    __half2 h = __floats2half2_rn(a, b);
    return *(uint32_t*)&h;
}

// ---------------- zero output + counters ----------------
__global__ __launch_bounds__(256) void zero_out_kernel(float* __restrict__ out)
{
    if (blockIdx.x == 0 && threadIdx.x < NEXP) g_counts[threadIdx.x] = 0;
    size_t i = ((size_t)blockIdx.x * blockDim.x + threadIdx.x) * 4;
    *(float4*)(out + i) = make_float4(0.f, 0.f, 0.f, 0.f);
}

// ---------------- preprocessing: streaming fp32 -> fp16 convert ----------------
__global__ __launch_bounds__(256) void convert_w_kernel(
    const float* __restrict__ wg, const float* __restrict__ wu,
    const float* __restrict__ wd)
{
    const int which = blockIdx.y;
    const float* src = (which == 0) ? wg : (which == 1) ? wu : wd;
    __half* dst = (which == 0) ? g_wg_h : (which == 1) ? g_wu_h : g_wd_h;
    size_t i = ((size_t)blockIdx.x * 256 + threadIdx.x) * 8;
    float4 v0 = *(const float4*)(src + i);
    float4 v1 = *(const float4*)(src + i + 4);
    uint4 o;
    o.x = hpack(v0.x, v0.y);
    o.y = hpack(v0.z, v0.w);
    o.z = hpack(v1.x, v1.y);
    o.w = hpack(v1.z, v1.w);
    *(uint4*)(dst + i) = o;
}

// ---------------- kernel 1: router (also emits x in fp16) ----------------
__global__ __launch_bounds__(256) void router_kernel(
    const float* __restrict__ x, const float* __restrict__ wr)
{
    int t = blockIdx.x;
    __shared__ float red[256][NEXP];
    float acc[NEXP];
#pragma unroll
    for (int e = 0; e < NEXP; e++) acc[e] = 0.f;
    const float* xr = x + (size_t)t * HIDDEN;
    __half* xh = g_x_h + (size_t)t * HIDDEN;
    for (int h = threadIdx.x; h < HIDDEN; h += 256) {
        float xv = xr[h];
        xh[h] = __float2half_rn(xv);
        const float* w = wr + (size_t)h * NEXP;
#pragma unroll
        for (int e = 0; e < NEXP; e++) acc[e] += xv * w[e];
    }
#pragma unroll
    for (int e = 0; e < NEXP; e++) red[threadIdx.x][e] = acc[e];
    __syncthreads();
    for (int s = 128; s > 0; s >>= 1) {
        if (threadIdx.x < s) {
#pragma unroll
            for (int e = 0; e < NEXP; e++)
                red[threadIdx.x][e] += red[threadIdx.x + s][e];
        }
        __syncthreads();
    }
    if (threadIdx.x == 0) {
        float l[NEXP];
#pragma unroll
        for (int e = 0; e < NEXP; e++) l[e] = red[0][e];
        int i0 = 0;
#pragma unroll
        for (int e = 1; e < NEXP; e++) if (l[e] > l[i0]) i0 = e;
        int i1 = -1;
#pragma unroll
        for (int e = 0; e < NEXP; e++) {
            if (e == i0) continue;
            if (i1 < 0 || l[e] > l[i1]) i1 = e;
        }
        float w0 = 1.f / (1.f + __expf(l[i1] - l[i0]));
        float w1 = 1.f - w0;
        int p0 = atomicAdd(&g_counts[i0], 1);
        g_pairs[i0 * TOKENS + p0] = (t << 1);
        int p1 = atomicAdd(&g_counts[i1], 1);
        g_pairs[i1 * TOKENS + p1] = (t << 1) | 1;
        g_wts[(t << 1)]     = w0;
        g_wts[(t << 1) | 1] = w1;
    }
}

// ---------------- kernel 2: grouped gate+up GEMM (fp16, 64m x 64n) ----------------
// fragment double-buffering: ldsm for ks+1 issued before MMAs of ks
__global__ __launch_bounds__(256, 2) void gateup_kernel()
{
    const int e   = blockIdx.z;
    const int cnt = g_counts[e];
    const int m0  = blockIdx.x * 64;
    if (m0 >= cnt) return;
    const int n0  = blockIdx.y * 64;

    extern __shared__ __align__(16) uint32_t dsm[];
    int* rows_sh = (int*)dsm;
    const uint32_t sb = (uint32_t)__cvta_generic_to_shared(dsm);

    const int tid  = threadIdx.x;
    const int wid  = tid >> 5;
    const int lane = tid & 31;
    const int gr   = lane >> 2;
    const int tg   = lane & 3;
    const int wm   = (wid & 1) * 32;   // warp m offset
    const int wq   = (wid >> 1);       // warp n-quarter (16 cols)

    if (tid < 64) {
        int m = m0 + tid;
        rows_sh[tid] = (m < cnt) ? g_pairs[e * TOKENS + m] : -1;
    }
    __syncthreads();

    const size_t eoff = (size_t)e * HIDDEN * INTER;

    // ---- staging (per thread): A 2 chunks, Bg 2, Bu 2 of 16B ----
    const __half* asrc[2];
    int  asz[2];
    uint32_t adst[2];
#pragma unroll
    for (int i = 0; i < 2; i++) {
        int q  = tid + 256 * i;
        int m  = q >> 3;
        int c  = q & 7;
        int pr = rows_sh[m];
        asz[i]  = (pr >= 0) ? 16 : 0;
        asrc[i] = g_x_h + (size_t)((pr >= 0) ? (pr >> 1) : 0) * HIDDEN + c * 8;
        adst[i] = (uint32_t)(m * 144 + c * 16);
    }
    const __half* bgsrc[2];
    const __half* busrc[2];
    uint32_t bdst[2];
#pragma unroll
    for (int i = 0; i < 2; i++) {
        int q  = tid + 256 * i;
        int kr = q >> 3;
        int c  = q & 7;
        bgsrc[i] = g_wg_h + eoff + (size_t)kr * INTER + n0 + c * 8;
        busrc[i] = g_wu_h + eoff + (size_t)kr * INTER + n0 + c * 8;
        bdst[i]  = (uint32_t)(kr * 144 + c * 16);
    }

    const int rlo    = lane & 15;
    const int kadd   = (lane >> 4) * 8;
    const int krow_l = ((lane >> 4) << 3) + (lane & 7);
    const int bcol_b = (wq * 16 + ((lane >> 3) & 1) * 8) * 2;

    float acc[2][4][4];
#pragma unroll
    for (int i = 0; i < 2; i++)
#pragma unroll
        for (int j = 0; j < 4; j++)
#pragma unroll
            for (int c = 0; c < 4; c++) acc[i][j][c] = 0.f;

#pragma unroll
    for (int s = 0; s < STAGES - 1; s++) {
        uint32_t ab = sb + 256 + s * STAGE_GU;
        uint32_t gb = ab + AT_B;
        uint32_t ub = gb + BGU_B;
        size_t koA = (size_t)s * KTH;
        size_t koB = (size_t)s * KTH * INTER;
#pragma unroll
        for (int i = 0; i < 2; i++) {
            cp16(ab + adst[i], asrc[i] + koA, asz[i]);
            cp16(gb + bdst[i], bgsrc[i] + koB, 16);
            cp16(ub + bdst[i], busrc[i] + koB, 16);
        }
        CP_COMMIT();
    }

    const int NT = HIDDEN / KTH;   // 32
    int rd = 0, wr = STAGES - 1;
    for (int kt = 0; kt < NT; kt++) {
        CP_WAIT1();
        __syncthreads();

        if (kt + STAGES - 1 < NT) {
            uint32_t ab = sb + 256 + wr * STAGE_GU;
            uint32_t gb = ab + AT_B;
            uint32_t ub = gb + BGU_B;
            size_t koA = (size_t)(kt + STAGES - 1) * KTH;
            size_t koB = koA * INTER;
#pragma unroll
            for (int i = 0; i < 2; i++) {
                cp16(ab + adst[i], asrc[i] + koA, asz[i]);
                cp16(gb + bdst[i], bgsrc[i] + koB, 16);
                cp16(ub + bdst[i], busrc[i] + koB, 16);
            }
        }
        CP_COMMIT();

        const uint32_t Ab = sb + 256 + rd * STAGE_GU;
        const uint32_t Gb = Ab + AT_B;
        const uint32_t Ub = Gb + BGU_B;

        // fragment double buffer: load ks=0, then prefetch ks+1 before MMA(ks)
        uint32_t af[2][2][4], bf[2][2][4];
        ldsm4 (af[0][0], Ab + (uint32_t)((wm + rlo)      * 144 + kadd * 2));
        ldsm4 (af[0][1], Ab + (uint32_t)((wm + 16 + rlo) * 144 + kadd * 2));
        ldsm4t(bf[0][0], Gb + (uint32_t)(krow_l * 144) + bcol_b);
        ldsm4t(bf[0][1], Ub + (uint32_t)(krow_l * 144) + bcol_b);
#pragma unroll
        for (int ks = 0; ks < 4; ks++) {
            const int cur = ks & 1, nxt = cur ^ 1;
            if (ks < 3) {
                const int k = (ks + 1) * 16;
                ldsm4 (af[nxt][0], Ab + (uint32_t)((wm + rlo)      * 144 + (k + kadd) * 2));
                ldsm4 (af[nxt][1], Ab + (uint32_t)((wm + 16 + rlo) * 144 + (k + kadd) * 2));
                ldsm4t(bf[nxt][0], Gb + (uint32_t)((k + krow_l) * 144) + bcol_b);
                ldsm4t(bf[nxt][1], Ub + (uint32_t)((k + krow_l) * 144) + bcol_b);
            }
#pragma unroll
            for (int mi = 0; mi < 2; mi++) {
                mma_f16(acc[mi][0], af[cur][mi], bf[cur][0][0], bf[cur][0][2]);
                mma_f16(acc[mi][1], af[cur][mi], bf[cur][0][1], bf[cur][0][3]);
                mma_f16(acc[mi][2], af[cur][mi], bf[cur][1][0], bf[cur][1][2]);
                mma_f16(acc[mi][3], af[cur][mi], bf[cur][1][1], bf[cur][1][3]);
            }
        }
        rd = (rd == STAGES - 1) ? 0 : rd + 1;
        wr = (wr == STAGES - 1) ? 0 : wr + 1;
    }

    // epilogue: silu(gate)*up*wt -> hbuf fp16 (nj 0,1 gate; 2,3 up at same cols)
    const int colbase = n0 + wq * 16 + 2 * tg;
#pragma unroll
    for (int mi = 0; mi < 2; mi++) {
#pragma unroll
        for (int half = 0; half < 2; half++) {
            int row = wm + mi * 16 + gr + half * 8;
            int pr  = rows_sh[row];
            if (pr < 0) continue;
            float wt = g_wts[pr];
            __half* hrow = g_hbuf_h + (size_t)pr * INTER;
#pragma unroll
            for (int nj = 0; nj < 2; nj++) {
                float g0 = acc[mi][nj][half * 2 + 0];
                float g1 = acc[mi][nj][half * 2 + 1];
                float u0 = acc[mi][nj + 2][half * 2 + 0];
                float u1 = acc[mi][nj + 2][half * 2 + 1];
                float h0 = (g0 / (1.f + __expf(-g0))) * u0 * wt;
                float h1 = (g1 / (1.f + __expf(-g1))) * u1 * wt;
                *(uint32_t*)&hrow[colbase + nj * 8] = hpack(h0, h1);
            }
        }
    }
}

// ---------------- kernel 3: grouped down GEMM (fp16, 64m x 128n) ----------------
__global__ __launch_bounds__(256, 2) void down_kernel(float* __restrict__ out)
{
    const int e   = blockIdx.z;
    const int cnt = g_counts[e];
    const int m0  = blockIdx.x * 64;
    if (m0 >= cnt) return;
    const int n0  = blockIdx.y * 128;

    extern __shared__ __align__(16) uint32_t dsm[];
    int* rows_sh = (int*)dsm;
    const uint32_t sb = (uint32_t)__cvta_generic_to_shared(dsm);

    const int tid  = threadIdx.x;
    const int wid  = tid >> 5;
    const int lane = tid & 31;
    const int gr   = lane >> 2;
    const int tg   = lane & 3;
    const int wm   = (wid & 1) * 32;
    const int wn   = (wid >> 1) * 32;

    if (tid < 64) {
        int m = m0 + tid;
        rows_sh[tid] = (m < cnt) ? g_pairs[e * TOKENS + m] : -1;
    }
    __syncthreads();

    const size_t eoff = (size_t)e * HIDDEN * INTER;

    const __half* asrc[2];
    int  asz[2];
    uint32_t adst[2];
#pragma unroll
    for (int i = 0; i < 2; i++) {
        int q  = tid + 256 * i;
        int m  = q >> 3;
        int c  = q & 7;
        int pr = rows_sh[m];
        asz[i]  = (pr >= 0) ? 16 : 0;
        asrc[i] = g_hbuf_h + (size_t)((pr >= 0) ? pr : 0) * INTER + c * 8;
        adst[i] = (uint32_t)(m * 144 + c * 16);
    }
    const __half* bsrc[4];
    uint32_t bdst[4];
#pragma unroll
    for (int i = 0; i < 4; i++) {
        int q  = tid + 256 * i;
        int kr = q >> 4;
        int c  = q & 15;
        bsrc[i] = g_wd_h + eoff + (size_t)kr * HIDDEN + n0 + c * 8;
        bdst[i] = (uint32_t)(kr * 272 + c * 16);
    }

    const int rlo    = lane & 15;
    const int kadd   = (lane >> 4) * 8;
    const int krow_l = ((lane >> 4) << 3) + (lane & 7);
    const int bsel_b = (((lane >> 3) & 1) * 8) * 2;

    float acc[2][4][4];
#pragma unroll
    for (int i = 0; i < 2; i++)
#pragma unroll
        for (int j = 0; j < 4; j++)
#pragma unroll
            for (int c = 0; c < 4; c++) acc[i][j][c] = 0.f;

#pragma unroll
    for (int s = 0; s < STAGES - 1; s++) {
        uint32_t ab = sb + 256 + s * STAGE_DN;
        uint32_t bb = ab + AT_B;
        size_t koA = (size_t)s * KTH;
        size_t koB = (size_t)s * KTH * HIDDEN;
#pragma unroll
        for (int i = 0; i < 2; i++) cp16(ab + adst[i], asrc[i] + koA, asz[i]);
#pragma unroll
        for (int i = 0; i < 4; i++) cp16(bb + bdst[i], bsrc[i] + koB, 16);
        CP_COMMIT();
    }

    const int NT = INTER / KTH;   // 22
    int rd = 0, wr = STAGES - 1;
    for (int kt = 0; kt < NT; kt++) {
        CP_WAIT1();
        __syncthreads();

        if (kt + STAGES - 1 < NT) {
            uint32_t ab = sb + 256 + wr * STAGE_DN;
            uint32_t bb = ab + AT_B;
            size_t koA = (size_t)(kt + STAGES - 1) * KTH;
            size_t koB = koA * HIDDEN;
#pragma unroll
            for (int i = 0; i < 2; i++) cp16(ab + adst[i], asrc[i] + koA, asz[i]);
#pragma unroll
            for (int i = 0; i < 4; i++) cp16(bb + bdst[i], bsrc[i] + koB, 16);
        }
        CP_COMMIT();

        const uint32_t Ab = sb + 256 + rd * STAGE_DN;
        const uint32_t Bb = Ab + AT_B;

        uint32_t af[2][2][4], bf[2][2][4];
        ldsm4 (af[0][0], Ab + (uint32_t)((wm + rlo)      * 144 + kadd * 2));
        ldsm4 (af[0][1], Ab + (uint32_t)((wm + 16 + rlo) * 144 + kadd * 2));
        ldsm4t(bf[0][0], Bb + (uint32_t)(krow_l * 272 + wn * 2) + bsel_b);
        ldsm4t(bf[0][1], Bb + (uint32_t)(krow_l * 272 + (wn + 16) * 2) + bsel_b);
#pragma unroll
        for (int ks = 0; ks < 4; ks++) {
            const int cur = ks & 1, nxt = cur ^ 1;
            if (ks < 3) {
                const int k = (ks + 1) * 16;
                ldsm4 (af[nxt][0], Ab + (uint32_t)((wm + rlo)      * 144 + (k + kadd) * 2));
                ldsm4 (af[nxt][1], Ab + (uint32_t)((wm + 16 + rlo) * 144 + (k + kadd) * 2));
                ldsm4t(bf[nxt][0], Bb + (uint32_t)((k + krow_l) * 272 + wn * 2) + bsel_b);
                ldsm4t(bf[nxt][1], Bb + (uint32_t)((k + krow_l) * 272 + (wn + 16) * 2) + bsel_b);
            }
#pragma unroll
            for (int mi = 0; mi < 2; mi++) {
                mma_f16(acc[mi][0], af[cur][mi], bf[cur][0][0], bf[cur][0][2]);
                mma_f16(acc[mi][1], af[cur][mi], bf[cur][0][1], bf[cur][0][3]);
                mma_f16(acc[mi][2], af[cur][mi], bf[cur][1][0], bf[cur][1][2]);
                mma_f16(acc[mi][3], af[cur][mi], bf[cur][1][1], bf[cur][1][3]);
            }
        }
        rd = (rd == STAGES - 1) ? 0 : rd + 1;
        wr = (wr == STAGES - 1) ? 0 : wr + 1;
    }

    // fused combine: atomicAdd both slots into out (2 adds/elem, commutative => deterministic)
    const int colbase = n0 + wn + 2 * tg;
#pragma unroll
    for (int mi = 0; mi < 2; mi++) {
#pragma unroll
        for (int half = 0; half < 2; half++) {
            int row = wm + mi * 16 + gr + half * 8;
            int pr  = rows_sh[row];
            if (pr < 0) continue;
            float* orow = out + (size_t)(pr >> 1) * HIDDEN;
#pragma unroll
            for (int nj = 0; nj < 4; nj++) {
                atomicAdd(&orow[colbase + nj * 8 + 0], acc[mi][nj][half * 2 + 0]);
                atomicAdd(&orow[colbase + nj * 8 + 1], acc[mi][nj][half * 2 + 1]);
            }
        }
    }
}

// ---------------- launch ----------------
extern "C" void kernel_launch(void* const* d_in, const int* in_sizes, int n_in,
                              void* d_out, int out_size)
{
    const float* x  = (const float*)d_in[0];
    const float* wr = (const float*)d_in[1];
    const float* wg = (const float*)d_in[2];
    const float* wu = (const float*)d_in[3];
    const float* wd = (const float*)d_in[4];
    float* out = (float*)d_out;

    cudaFuncSetAttribute(gateup_kernel, cudaFuncAttributeMaxDynamicSharedMemorySize, SMEM_GU);
    cudaFuncSetAttribute(down_kernel,  cudaFuncAttributeMaxDynamicSharedMemorySize, SMEM_DN);

    zero_out_kernel<<<(TOKENS * HIDDEN) / (256 * 4), 256>>>(out);
    router_kernel<<<TOKENS, 256>>>(x, wr);

    const int welems = NEXP * HIDDEN * INTER;                 // 23,068,672
    convert_w_kernel<<<dim3(welems / (256 * 8), 3), 256>>>(wg, wu, wd);

    dim3 g1(TOKENS / 64, INTER / 64, NEXP);     // m fastest: L2 B-tile sharing
    gateup_kernel<<<g1, 256, SMEM_GU>>>();

    dim3 g2(TOKENS / 64, HIDDEN / 128, NEXP);   // m fastest
    down_kernel<<<g2, 256, SMEM_DN>>>(out);
}

// round 16
// speedup vs baseline: 1.0013x; 1.0013x over previous
#include <cuda_runtime.h>
#include <cuda_fp16.h>
#include <cstdint>
#include <math.h>

#define TOKENS 2048
#define HIDDEN 2048
#define INTER  1408
#define NEXP   8
#define KTH    64          // k elements per tile (halfs) = 128B of data per row
#define STAGES 3

// gateup tiles: A [64m][64k] stride 144B; Bg/Bu [64k][64n] stride 144B
#define AT_B      (64 * 144)               // 9216
#define BGU_B     (64 * 144)               // 9216 per gate/up tile
#define STAGE_GU  (AT_B + 2 * BGU_B)       // 27648
#define SMEM_GU   (256 + STAGES * STAGE_GU)   // 83200
// down tiles: A [64m][64k] stride 144B; B [64k][128n] stride 272B
#define BDN_B     (64 * 272)               // 17408
#define STAGE_DN  (AT_B + BDN_B)           // 26624
#define SMEM_DN   (256 + STAGES * STAGE_DN)   // 80128

// ---------------- device scratch (no allocation) ----------------
__device__ int    g_counts[NEXP];
__device__ int    g_pairs[NEXP * TOKENS];                 // encoded (t<<1)|slot
__device__ float  g_wts[TOKENS * 2];                      // combine weight per (t,slot)
__device__ __half g_x_h[(size_t)TOKENS * HIDDEN];         // x in fp16
__device__ __half g_wg_h[(size_t)NEXP * HIDDEN * INTER];  // w_gate fp16, [e][k][n]
__device__ __half g_wu_h[(size_t)NEXP * HIDDEN * INTER];  // w_up   fp16, [e][k][n]
__device__ __half g_wd_h[(size_t)NEXP * INTER * HIDDEN];  // w_down fp16, [e][k][n]
__device__ __half g_hbuf_h[(size_t)TOKENS * 2 * INTER];   // gated intermediate fp16

// m16n8k16 fp16 MMA, fp32 accumulate (standard PTX, sm_80+)
__device__ __forceinline__ void mma_f16(float* c, const uint32_t* a,
                                        uint32_t b0, uint32_t b1) {
    asm volatile(
        "mma.sync.aligned.m16n8k16.row.col.f32.f16.f16.f32 "
        "{%0,%1,%2,%3}, {%4,%5,%6,%7}, {%8,%9}, {%0,%1,%2,%3};"
        : "+f"(c[0]), "+f"(c[1]), "+f"(c[2]), "+f"(c[3])
        : "r"(a[0]), "r"(a[1]), "r"(a[2]), "r"(a[3]), "r"(b0), "r"(b1));
}

__device__ __forceinline__ void ldsm4(uint32_t* r, uint32_t addr) {
    asm volatile("ldmatrix.sync.aligned.m8n8.x4.shared.b16 {%0,%1,%2,%3}, [%4];"
        : "=r"(r[0]), "=r"(r[1]), "=r"(r[2]), "=r"(r[3]) : "r"(addr));
}
// transposed variant: stored [k][n] (n contiguous), yields col-major B fragment
__device__ __forceinline__ void ldsm4t(uint32_t* r, uint32_t addr) {
    asm volatile("ldmatrix.sync.aligned.m8n8.x4.trans.shared.b16 {%0,%1,%2,%3}, [%4];"
        : "=r"(r[0]), "=r"(r[1]), "=r"(r[2]), "=r"(r[3]) : "r"(addr));
}

__device__ __forceinline__ void cp16(uint32_t dst, const void* src, int sz) {
    asm volatile("cp.async.cg.shared.global [%0], [%1], 16, %2;"
                 :: "r"(dst), "l"(src), "r"(sz) : "memory");
}
#define CP_COMMIT() asm volatile("cp.async.commit_group;" ::: "memory")
#define CP_WAIT1()  asm volatile("cp.async.wait_group 1;" ::: "memory")

__device__ __forceinline__ uint32_t hpack(float a, float b) {
    __half2 h = __floats2half2_rn(a, b);
    return *(uint32_t*)&h;
}

// ---------------- zero output + counters ----------------
__global__ __launch_bounds__(256) void zero_out_kernel(float* __restrict__ out)
{
    if (blockIdx.x == 0 && threadIdx.x < NEXP) g_counts[threadIdx.x] = 0;
    size_t i = ((size_t)blockIdx.x * blockDim.x + threadIdx.x) * 4;
    *(float4*)(out + i) = make_float4(0.f, 0.f, 0.f, 0.f);
}

// ---------------- preprocessing: streaming fp32 -> fp16 convert ----------------
__global__ __launch_bounds__(256) void convert_w_kernel(
    const float* __restrict__ wg, const float* __restrict__ wu,
    const float* __restrict__ wd)
{
    const int which = blockIdx.y;
    const float* src = (which == 0) ? wg : (which == 1) ? wu : wd;
    __half* dst = (which == 0) ? g_wg_h : (which == 1) ? g_wu_h : g_wd_h;
    size_t i = ((size_t)blockIdx.x * 256 + threadIdx.x) * 8;
    float4 v0 = *(const float4*)(src + i);
    float4 v1 = *(const float4*)(src + i + 4);
    uint4 o;
    o.x = hpack(v0.x, v0.y);
    o.y = hpack(v0.z, v0.w);
    o.z = hpack(v1.x, v1.y);
    o.w = hpack(v1.z, v1.w);
    *(uint4*)(dst + i) = o;
}

// ---------------- kernel 1: router (also emits x in fp16) ----------------
__global__ __launch_bounds__(256) void router_kernel(
    const float* __restrict__ x, const float* __restrict__ wr)
{
    int t = blockIdx.x;
    __shared__ float red[256][NEXP];
    float acc[NEXP];
#pragma unroll
    for (int e = 0; e < NEXP; e++) acc[e] = 0.f;
    const float* xr = x + (size_t)t * HIDDEN;
    __half* xh = g_x_h + (size_t)t * HIDDEN;
    for (int h = threadIdx.x; h < HIDDEN; h += 256) {
        float xv = xr[h];
        xh[h] = __float2half_rn(xv);
        const float* w = wr + (size_t)h * NEXP;
#pragma unroll
        for (int e = 0; e < NEXP; e++) acc[e] += xv * w[e];
    }
#pragma unroll
    for (int e = 0; e < NEXP; e++) red[threadIdx.x][e] = acc[e];
    __syncthreads();
    for (int s = 128; s > 0; s >>= 1) {
        if (threadIdx.x < s) {
#pragma unroll
            for (int e = 0; e < NEXP; e++)
                red[threadIdx.x][e] += red[threadIdx.x + s][e];
        }
        __syncthreads();
    }
    if (threadIdx.x == 0) {
        float l[NEXP];
#pragma unroll
        for (int e = 0; e < NEXP; e++) l[e] = red[0][e];
        int i0 = 0;
#pragma unroll
        for (int e = 1; e < NEXP; e++) if (l[e] > l[i0]) i0 = e;
        int i1 = -1;
#pragma unroll
        for (int e = 0; e < NEXP; e++) {
            if (e == i0) continue;
            if (i1 < 0 || l[e] > l[i1]) i1 = e;
        }
        float w0 = 1.f / (1.f + __expf(l[i1] - l[i0]));
        float w1 = 1.f - w0;
        int p0 = atomicAdd(&g_counts[i0], 1);
        g_pairs[i0 * TOKENS + p0] = (t << 1);
        int p1 = atomicAdd(&g_counts[i1], 1);
        g_pairs[i1 * TOKENS + p1] = (t << 1) | 1;
        g_wts[(t << 1)]     = w0;
        g_wts[(t << 1) | 1] = w1;
    }
}

// ---------------- kernel 2: grouped gate+up GEMM (fp16, 64m x 64n) ----------------
// fragment double-buffering: ldsm for ks+1 issued before MMAs of ks
__global__ __launch_bounds__(256, 2) void gateup_kernel()
{
    const int e   = blockIdx.z;
    const int cnt = g_counts[e];
    const int m0  = blockIdx.x * 64;
    if (m0 >= cnt) return;
    const int n0  = blockIdx.y * 64;

    extern __shared__ __align__(16) uint32_t dsm[];
    int* rows_sh = (int*)dsm;
    const uint32_t sb = (uint32_t)__cvta_generic_to_shared(dsm);

    const int tid  = threadIdx.x;
    const int wid  = tid >> 5;
    const int lane = tid & 31;
    const int gr   = lane >> 2;
    const int tg   = lane & 3;
    const int wm   = (wid & 1) * 32;   // warp m offset
    const int wq   = (wid >> 1);       // warp n-quarter (16 cols)

    if (tid < 64) {
        int m = m0 + tid;
        rows_sh[tid] = (m < cnt) ? g_pairs[e * TOKENS + m] : -1;
    }
    __syncthreads();

    const size_t eoff = (size_t)e * HIDDEN * INTER;

    // ---- staging (per thread): A 2 chunks, Bg 2, Bu 2 of 16B ----
    const __half* asrc[2];
    int  asz[2];
    uint32_t adst[2];
#pragma unroll
    for (int i = 0; i < 2; i++) {
        int q  = tid + 256 * i;
        int m  = q >> 3;
        int c  = q & 7;
        int pr = rows_sh[m];
        asz[i]  = (pr >= 0) ? 16 : 0;
        asrc[i] = g_x_h + (size_t)((pr >= 0) ? (pr >> 1) : 0) * HIDDEN + c * 8;
        adst[i] = (uint32_t)(m * 144 + c * 16);
    }
    const __half* bgsrc[2];
    const __half* busrc[2];
    uint32_t bdst[2];
#pragma unroll
    for (int i = 0; i < 2; i++) {
        int q  = tid + 256 * i;
        int kr = q >> 3;
        int c  = q & 7;
        bgsrc[i] = g_wg_h + eoff + (size_t)kr * INTER + n0 + c * 8;
        busrc[i] = g_wu_h + eoff + (size_t)kr * INTER + n0 + c * 8;
        bdst[i]  = (uint32_t)(kr * 144 + c * 16);
    }

    const int rlo    = lane & 15;
    const int kadd   = (lane >> 4) * 8;
    const int krow_l = ((lane >> 4) << 3) + (lane & 7);
    const int bcol_b = (wq * 16 + ((lane >> 3) & 1) * 8) * 2;

    float acc[2][4][4];
#pragma unroll
    for (int i = 0; i < 2; i++)
#pragma unroll
        for (int j = 0; j < 4; j++)
#pragma unroll
            for (int c = 0; c < 4; c++) acc[i][j][c] = 0.f;

#pragma unroll
    for (int s = 0; s < STAGES - 1; s++) {
        uint32_t ab = sb + 256 + s * STAGE_GU;
        uint32_t gb = ab + AT_B;
        uint32_t ub = gb + BGU_B;
        size_t koA = (size_t)s * KTH;
        size_t koB = (size_t)s * KTH * INTER;
#pragma unroll
        for (int i = 0; i < 2; i++) {
            cp16(ab + adst[i], asrc[i] + koA, asz[i]);
            cp16(gb + bdst[i], bgsrc[i] + koB, 16);
            cp16(ub + bdst[i], busrc[i] + koB, 16);
        }
        CP_COMMIT();
    }

    const int NT = HIDDEN / KTH;   // 32
    int rd = 0, wr = STAGES - 1;
    for (int kt = 0; kt < NT; kt++) {
        CP_WAIT1();
        __syncthreads();

        if (kt + STAGES - 1 < NT) {
            uint32_t ab = sb + 256 + wr * STAGE_GU;
            uint32_t gb = ab + AT_B;
            uint32_t ub = gb + BGU_B;
            size_t koA = (size_t)(kt + STAGES - 1) * KTH;
            size_t koB = koA * INTER;
#pragma unroll
            for (int i = 0; i < 2; i++) {
                cp16(ab + adst[i], asrc[i] + koA, asz[i]);
                cp16(gb + bdst[i], bgsrc[i] + koB, 16);
                cp16(ub + bdst[i], busrc[i] + koB, 16);
            }
        }
        CP_COMMIT();

        const uint32_t Ab = sb + 256 + rd * STAGE_GU;
        const uint32_t Gb = Ab + AT_B;
        const uint32_t Ub = Gb + BGU_B;

        // fragment double buffer: load ks=0, then prefetch ks+1 before MMA(ks)
        uint32_t af[2][2][4], bf[2][2][4];
        ldsm4 (af[0][0], Ab + (uint32_t)((wm + rlo)      * 144 + kadd * 2));
        ldsm4 (af[0][1], Ab + (uint32_t)((wm + 16 + rlo) * 144 + kadd * 2));
        ldsm4t(bf[0][0], Gb + (uint32_t)(krow_l * 144) + bcol_b);
        ldsm4t(bf[0][1], Ub + (uint32_t)(krow_l * 144) + bcol_b);
#pragma unroll
        for (int ks = 0; ks < 4; ks++) {
            const int cur = ks & 1, nxt = cur ^ 1;
            if (ks < 3) {
                const int k = (ks + 1) * 16;
                ldsm4 (af[nxt][0], Ab + (uint32_t)((wm + rlo)      * 144 + (k + kadd) * 2));
                ldsm4 (af[nxt][1], Ab + (uint32_t)((wm + 16 + rlo) * 144 + (k + kadd) * 2));
                ldsm4t(bf[nxt][0], Gb + (uint32_t)((k + krow_l) * 144) + bcol_b);
                ldsm4t(bf[nxt][1], Ub + (uint32_t)((k + krow_l) * 144) + bcol_b);
            }
#pragma unroll
            for (int mi = 0; mi < 2; mi++) {
                mma_f16(acc[mi][0], af[cur][mi], bf[cur][0][0], bf[cur][0][2]);
                mma_f16(acc[mi][1], af[cur][mi], bf[cur][0][1], bf[cur][0][3]);
                mma_f16(acc[mi][2], af[cur][mi], bf[cur][1][0], bf[cur][1][2]);
                mma_f16(acc[mi][3], af[cur][mi], bf[cur][1][1], bf[cur][1][3]);
            }
        }
        rd = (rd == STAGES - 1) ? 0 : rd + 1;
        wr = (wr == STAGES - 1) ? 0 : wr + 1;
    }

    // epilogue: silu(gate)*up*wt -> hbuf fp16 (nj 0,1 gate; 2,3 up at same cols)
    const int colbase = n0 + wq * 16 + 2 * tg;
#pragma unroll
    for (int mi = 0; mi < 2; mi++) {
#pragma unroll
        for (int half = 0; half < 2; half++) {
            int row = wm + mi * 16 + gr + half * 8;
            int pr  = rows_sh[row];
            if (pr < 0) continue;
            float wt = g_wts[pr];
            __half* hrow = g_hbuf_h + (size_t)pr * INTER;
#pragma unroll
            for (int nj = 0; nj < 2; nj++) {
                float g0 = acc[mi][nj][half * 2 + 0];
                float g1 = acc[mi][nj][half * 2 + 1];
                float u0 = acc[mi][nj + 2][half * 2 + 0];
                float u1 = acc[mi][nj + 2][half * 2 + 1];
                float h0 = (g0 / (1.f + __expf(-g0))) * u0 * wt;
                float h1 = (g1 / (1.f + __expf(-g1))) * u1 * wt;
                *(uint32_t*)&hrow[colbase + nj * 8] = hpack(h0, h1);
            }
        }
    }
}

// ---------------- kernel 3: grouped down GEMM (fp16, 64m x 128n) ----------------
__global__ __launch_bounds__(256, 2) void down_kernel(float* __restrict__ out)
{
    const int e   = blockIdx.z;
    const int cnt = g_counts[e];
    const int m0  = blockIdx.x * 64;
    if (m0 >= cnt) return;
    const int n0  = blockIdx.y * 128;

    extern __shared__ __align__(16) uint32_t dsm[];
    int* rows_sh = (int*)dsm;
    const uint32_t sb = (uint32_t)__cvta_generic_to_shared(dsm);

    const int tid  = threadIdx.x;
    const int wid  = tid >> 5;
    const int lane = tid & 31;
    const int gr   = lane >> 2;
    const int tg   = lane & 3;
    const int wm   = (wid & 1) * 32;
    const int wn   = (wid >> 1) * 32;

    if (tid < 64) {
        int m = m0 + tid;
        rows_sh[tid] = (m < cnt) ? g_pairs[e * TOKENS + m] : -1;
    }
    __syncthreads();

    const size_t eoff = (size_t)e * HIDDEN * INTER;

    const __half* asrc[2];
    int  asz[2];
    uint32_t adst[2];
#pragma unroll
    for (int i = 0; i < 2; i++) {
        int q  = tid + 256 * i;
        int m  = q >> 3;
        int c  = q & 7;
        int pr = rows_sh[m];
        asz[i]  = (pr >= 0) ? 16 : 0;
        asrc[i] = g_hbuf_h + (size_t)((pr >= 0) ? pr : 0) * INTER + c * 8;
        adst[i] = (uint32_t)(m * 144 + c * 16);
    }
    const __half* bsrc[4];
    uint32_t bdst[4];
#pragma unroll
    for (int i = 0; i < 4; i++) {
        int q  = tid + 256 * i;
        int kr = q >> 4;
        int c  = q & 15;
        bsrc[i] = g_wd_h + eoff + (size_t)kr * HIDDEN + n0 + c * 8;
        bdst[i] = (uint32_t)(kr * 272 + c * 16);
    }

    const int rlo    = lane & 15;
    const int kadd   = (lane >> 4) * 8;
    const int krow_l = ((lane >> 4) << 3) + (lane & 7);
    const int bsel_b = (((lane >> 3) & 1) * 8) * 2;

    float acc[2][4][4];
#pragma unroll
    for (int i = 0; i < 2; i++)
#pragma unroll
        for (int j = 0; j < 4; j++)
#pragma unroll
            for (int c = 0; c < 4; c++) acc[i][j][c] = 0.f;

#pragma unroll
    for (int s = 0; s < STAGES - 1; s++) {
        uint32_t ab = sb + 256 + s * STAGE_DN;
        uint32_t bb = ab + AT_B;
        size_t koA = (size_t)s * KTH;
        size_t koB = (size_t)s * KTH * HIDDEN;
#pragma unroll
        for (int i = 0; i < 2; i++) cp16(ab + adst[i], asrc[i] + koA, asz[i]);
#pragma unroll
        for (int i = 0; i < 4; i++) cp16(bb + bdst[i], bsrc[i] + koB, 16);
        CP_COMMIT();
    }

    const int NT = INTER / KTH;   // 22
    int rd = 0, wr = STAGES - 1;
    for (int kt = 0; kt < NT; kt++) {
        CP_WAIT1();
        __syncthreads();

        if (kt + STAGES - 1 < NT) {
            uint32_t ab = sb + 256 + wr * STAGE_DN;
            uint32_t bb = ab + AT_B;
            size_t koA = (size_t)(kt + STAGES - 1) * KTH;
            size_t koB = koA * HIDDEN;
#pragma unroll
            for (int i = 0; i < 2; i++) cp16(ab + adst[i], asrc[i] + koA, asz[i]);
#pragma unroll
            for (int i = 0; i < 4; i++) cp16(bb + bdst[i], bsrc[i] + koB, 16);
        }
        CP_COMMIT();

        const uint32_t Ab = sb + 256 + rd * STAGE_DN;
        const uint32_t Bb = Ab + AT_B;

        uint32_t af[2][2][4], bf[2][2][4];
        ldsm4 (af[0][0], Ab + (uint32_t)((wm + rlo)      * 144 + kadd * 2));
        ldsm4 (af[0][1], Ab + (uint32_t)((wm + 16 + rlo) * 144 + kadd * 2));
        ldsm4t(bf[0][0], Bb + (uint32_t)(krow_l * 272 + wn * 2) + bsel_b);
        ldsm4t(bf[0][1], Bb + (uint32_t)(krow_l * 272 + (wn + 16) * 2) + bsel_b);
#pragma unroll
        for (int ks = 0; ks < 4; ks++) {
            const int cur = ks & 1, nxt = cur ^ 1;
            if (ks < 3) {
                const int k = (ks + 1) * 16;
                ldsm4 (af[nxt][0], Ab + (uint32_t)((wm + rlo)      * 144 + (k + kadd) * 2));
                ldsm4 (af[nxt][1], Ab + (uint32_t)((wm + 16 + rlo) * 144 + (k + kadd) * 2));
                ldsm4t(bf[nxt][0], Bb + (uint32_t)((k + krow_l) * 272 + wn * 2) + bsel_b);
                ldsm4t(bf[nxt][1], Bb + (uint32_t)((k + krow_l) * 272 + (wn + 16) * 2) + bsel_b);
            }
#pragma unroll
            for (int mi = 0; mi < 2; mi++) {
                mma_f16(acc[mi][0], af[cur][mi], bf[cur][0][0], bf[cur][0][2]);
                mma_f16(acc[mi][1], af[cur][mi], bf[cur][0][1], bf[cur][0][3]);
                mma_f16(acc[mi][2], af[cur][mi], bf[cur][1][0], bf[cur][1][2]);
                mma_f16(acc[mi][3], af[cur][mi], bf[cur][1][1], bf[cur][1][3]);
            }
        }
        rd = (rd == STAGES - 1) ? 0 : rd + 1;
        wr = (wr == STAGES - 1) ? 0 : wr + 1;
    }

    // fused combine: atomicAdd both slots into out (2 adds/elem, commutative => deterministic)
    const int colbase = n0 + wn + 2 * tg;
#pragma unroll
    for (int mi = 0; mi < 2; mi++) {
#pragma unroll
        for (int half = 0; half < 2; half++) {
            int row = wm + mi * 16 + gr + half * 8;
            int pr  = rows_sh[row];
            if (pr < 0) continue;
            float* orow = out + (size_t)(pr >> 1) * HIDDEN;
#pragma unroll
            for (int nj = 0; nj < 4; nj++) {
                atomicAdd(&orow[colbase + nj * 8 + 0], acc[mi][nj][half * 2 + 0]);
                atomicAdd(&orow[colbase + nj * 8 + 1], acc[mi][nj][half * 2 + 1]);
            }
        }
    }
}

// ---------------- launch ----------------
extern "C" void kernel_launch(void* const* d_in, const int* in_sizes, int n_in,
                              void* d_out, int out_size)
{
    const float* x  = (const float*)d_in[0];
    const float* wr = (const float*)d_in[1];
    const float* wg = (const float*)d_in[2];
    const float* wu = (const float*)d_in[3];
    const float* wd = (const float*)d_in[4];
    float* out = (float*)d_out;

    cudaFuncSetAttribute(gateup_kernel, cudaFuncAttributeMaxDynamicSharedMemorySize, SMEM_GU);
    cudaFuncSetAttribute(down_kernel,  cudaFuncAttributeMaxDynamicSharedMemorySize, SMEM_DN);

    zero_out_kernel<<<(TOKENS * HIDDEN) / (256 * 4), 256>>>(out);
    router_kernel<<<TOKENS, 256>>>(x, wr);

    const int welems = NEXP * HIDDEN * INTER;                 // 23,068,672
    convert_w_kernel<<<dim3(welems / (256 * 8), 3), 256>>>(wg, wu, wd);

    dim3 g1(TOKENS / 64, INTER / 64, NEXP);     // m fastest: L2 B-tile sharing
    gateup_kernel<<<g1, 256, SMEM_GU>>>();

    dim3 g2(TOKENS / 64, HIDDEN / 128, NEXP);   // m fastest
    down_kernel<<<g2, 256, SMEM_DN>>>(out);
}